// round 13
// baseline (speedup 1.0000x reference)
#include <cuda_runtime.h>
#include <cuda_fp16.h>
#include <cstdint>

// EdgeNetwork R13 — fp16 mma.sync, zero-smem data plane.
// A fragments gathered DIRECTLY from global (node/attr rows are L2-resident);
// X never touches smem. B (weights) relaid out for conflict-free LDS.64
// fragment loads (col n stored at (n&7)*8 + (n>>3), stride 66).
// 8 warps x 16 edges, warp-autonomous; smem = weights+params only (29KB).

#define WQS 66    // W pair-row stride (words); (qc*33+4qr+j) mod 16 bijective
#define TPB 4

__device__ __forceinline__ uint32_t h2pack(float lo, float hi) {
    __half2 h = __floats2half2_rn(lo, hi);
    return *(uint32_t*)&h;
}

#define MMA_F16(d, a, b0, b1) \
    asm volatile("mma.sync.aligned.m16n8k16.row.col.f32.f16.f16.f32 " \
        "{%0,%1,%2,%3}, {%4,%5,%6,%7}, {%8,%9}, {%0,%1,%2,%3};" \
        : "+f"((d)[0]), "+f"((d)[1]), "+f"((d)[2]), "+f"((d)[3]) \
        : "r"((a)[0]), "r"((a)[1]), "r"((a)[2]), "r"((a)[3]), "r"(b0), "r"(b1))

__global__ __launch_bounds__(256, 3)
void edgenet_mma(const float* __restrict__ nodef,
                 const int* __restrict__ eidx,
                 const float* __restrict__ eattr,
                 const float* __restrict__ W1, const float* __restrict__ pB1,
                 const float* __restrict__ G1, const float* __restrict__ BE1,
                 const float* __restrict__ W2, const float* __restrict__ pB2,
                 const float* __restrict__ G2, const float* __restrict__ BE2,
                 const float* __restrict__ W3, const float* __restrict__ pB3,
                 float* __restrict__ out, int E, int nNodes)
{
    __shared__ uint32_t W1q[72 * WQS];
    __shared__ uint32_t W2q[32 * WQS];
    __shared__ float    prm[452];

    const int tid  = threadIdx.x;
    const int lane = tid & 31;
    const int wid  = tid >> 5;
    const int qr   = lane >> 2;    // 0..7
    const int qc   = lane & 3;     // 0..3

    // ---- stage weights: k-pair half2, col n -> (n&7)*8 + (n>>3) ----
    for (int i = tid; i < 72 * 64; i += 256) {
        int p = i >> 6, n = i & 63;
        W1q[p * WQS + (n & 7) * 8 + (n >> 3)] =
            h2pack(W1[(2 * p) * 64 + n], W1[(2 * p + 1) * 64 + n]);
    }
    for (int i = tid; i < 32 * 64; i += 256) {
        int p = i >> 6, n = i & 63;
        W2q[p * WQS + (n & 7) * 8 + (n >> 3)] =
            h2pack(W2[(2 * p) * 64 + n], W2[(2 * p + 1) * 64 + n]);
    }
    if (tid < 64) {
        prm[tid]       = pB1[tid];
        prm[64 + tid]  = G1[tid];
        prm[128 + tid] = BE1[tid];
        prm[192 + tid] = pB2[tid];
        prm[256 + tid] = G2[tid];
        prm[320 + tid] = BE2[tid];
        prm[384 + tid] = W3[tid];
    }
    if (tid == 0) prm[448] = pB3[0];
    __syncthreads();   // only CTA barrier

    const int rBase = wid * 16;

    for (int it = 0; it < TPB; ++it) {
        const int eBase = (blockIdx.x * TPB + it) * 128;
        if (eBase >= E) break;

        // ---- per-tile row pointers (2 edges per thread: qr, qr+8) ----
        int eLo = eBase + rBase + qr;
        int eHi = eLo + 8;
        int eLoC = (eLo < E) ? eLo : (E - 1);
        int eHiC = (eHi < E) ? eHi : (E - 1);
        int sLo = eidx[eLoC], dLo = eidx[(size_t)E + eLoC];
        int sHi = eidx[eHiC], dHi = eidx[(size_t)E + eHiC];
        sLo = max(0, min(sLo, nNodes - 1));
        dLo = max(0, min(dLo, nNodes - 1));
        sHi = max(0, min(sHi, nNodes - 1));
        dHi = max(0, min(dHi, nNodes - 1));
        const float* srcLo  = nodef + (size_t)sLo * 64;
        const float* srcHi  = nodef + (size_t)sHi * 64;
        const float* dstLo  = nodef + (size_t)dLo * 64;
        const float* dstHi  = nodef + (size_t)dHi * 64;
        const float* attrLo = eattr + (size_t)eLoC * 16;
        const float* attrHi = eattr + (size_t)eHiC * 16;

        // ===== GEMM1: X[16,144] @ W1, A straight from global =====
        float acc[8][4];
        #pragma unroll
        for (int nt = 0; nt < 8; ++nt)
            #pragma unroll
            for (int x = 0; x < 4; ++x) acc[nt][x] = 0.f;

        #pragma unroll
        for (int ks = 0; ks < 9; ++ks) {
            const float* pLo;
            const float* pHi;
            int fo;
            if (ks < 4)      { pLo = srcLo;  pHi = srcHi;  fo = 16 * ks + 2 * qc; }
            else if (ks < 8) { pLo = dstLo;  pHi = dstHi;  fo = 16 * (ks - 4) + 2 * qc; }
            else             { pLo = attrLo; pHi = attrHi; fo = 2 * qc; }
            float2 v0 = *(const float2*)(pLo + fo);
            float2 v1 = *(const float2*)(pHi + fo);
            float2 v2 = *(const float2*)(pLo + fo + 8);
            float2 v3 = *(const float2*)(pHi + fo + 8);
            uint32_t a[4];
            a[0] = h2pack(v0.x, v0.y);
            a[1] = h2pack(v1.x, v1.y);
            a[2] = h2pack(v2.x, v2.y);
            a[3] = h2pack(v3.x, v3.y);
            const uint32_t* wbA = W1q + (8 * ks + qc) * WQS + qr * 8;
            const uint32_t* wbB = wbA + 4 * WQS;
            #pragma unroll
            for (int g = 0; g < 4; ++g) {
                uint2 b0 = *(const uint2*)(wbA + 2 * g);
                uint2 b1 = *(const uint2*)(wbB + 2 * g);
                MMA_F16(acc[2 * g],     a, b0.x, b1.x);
                MMA_F16(acc[2 * g + 1], a, b0.y, b1.y);
            }
        }

        // ---- LN1 + leaky, in-register -> GEMM2 A fragments ----
        uint32_t a2[4][4];
        {
            float s0 = 0.f, ss0 = 0.f, s1 = 0.f, ss1 = 0.f;
            #pragma unroll
            for (int nt = 0; nt < 8; ++nt) {
                int colb = nt * 8 + 2 * qc;
                float v0 = acc[nt][0] + prm[colb];
                float v1 = acc[nt][1] + prm[colb + 1];
                float v2 = acc[nt][2] + prm[colb];
                float v3 = acc[nt][3] + prm[colb + 1];
                acc[nt][0] = v0; acc[nt][1] = v1; acc[nt][2] = v2; acc[nt][3] = v3;
                s0 += v0 + v1; ss0 += v0 * v0 + v1 * v1;
                s1 += v2 + v3; ss1 += v2 * v2 + v3 * v3;
            }
            #pragma unroll
            for (int o = 1; o <= 2; o <<= 1) {
                s0  += __shfl_xor_sync(0xffffffffu, s0,  o);
                ss0 += __shfl_xor_sync(0xffffffffu, ss0, o);
                s1  += __shfl_xor_sync(0xffffffffu, s1,  o);
                ss1 += __shfl_xor_sync(0xffffffffu, ss1, o);
            }
            float mu0 = s0 * (1.f / 64.f);
            float rs0 = rsqrtf(ss0 * (1.f / 64.f) - mu0 * mu0 + 1e-5f);
            float mu1 = s1 * (1.f / 64.f);
            float rs1 = rsqrtf(ss1 * (1.f / 64.f) - mu1 * mu1 + 1e-5f);
            #pragma unroll
            for (int nt = 0; nt < 8; ++nt) {
                int colb = nt * 8 + 2 * qc;
                float g0 = prm[64 + colb], g1 = prm[64 + colb + 1];
                float e0 = prm[128 + colb], e1 = prm[128 + colb + 1];
                float y0 = (acc[nt][0] - mu0) * rs0 * g0 + e0;
                float y1 = (acc[nt][1] - mu0) * rs0 * g1 + e1;
                float y2 = (acc[nt][2] - mu1) * rs1 * g0 + e0;
                float y3 = (acc[nt][3] - mu1) * rs1 * g1 + e1;
                y0 = (y0 < 0.f) ? 0.1f * y0 : y0;
                y1 = (y1 < 0.f) ? 0.1f * y1 : y1;
                y2 = (y2 < 0.f) ? 0.1f * y2 : y2;
                y3 = (y3 < 0.f) ? 0.1f * y3 : y3;
                a2[nt >> 1][(nt & 1) * 2]     = h2pack(y0, y1);
                a2[nt >> 1][(nt & 1) * 2 + 1] = h2pack(y2, y3);
            }
        }

        // ===== GEMM2: H[16,64] @ W2 (A in registers) =====
        float ac2[8][4];
        #pragma unroll
        for (int nt = 0; nt < 8; ++nt)
            #pragma unroll
            for (int x = 0; x < 4; ++x) ac2[nt][x] = 0.f;

        #pragma unroll
        for (int ks = 0; ks < 4; ++ks) {
            const uint32_t* wbA = W2q + (8 * ks + qc) * WQS + qr * 8;
            const uint32_t* wbB = wbA + 4 * WQS;
            #pragma unroll
            for (int g = 0; g < 4; ++g) {
                uint2 b0 = *(const uint2*)(wbA + 2 * g);
                uint2 b1 = *(const uint2*)(wbB + 2 * g);
                MMA_F16(ac2[2 * g],     a2[ks], b0.x, b1.x);
                MMA_F16(ac2[2 * g + 1], a2[ks], b0.y, b1.y);
            }
        }

        // ---- LN2 + leaky + W3 dot + store (shfl-only) ----
        {
            float s0 = 0.f, ss0 = 0.f, s1 = 0.f, ss1 = 0.f;
            #pragma unroll
            for (int nt = 0; nt < 8; ++nt) {
                int colb = nt * 8 + 2 * qc;
                float v0 = ac2[nt][0] + prm[192 + colb];
                float v1 = ac2[nt][1] + prm[192 + colb + 1];
                float v2 = ac2[nt][2] + prm[192 + colb];
                float v3 = ac2[nt][3] + prm[192 + colb + 1];
                ac2[nt][0] = v0; ac2[nt][1] = v1; ac2[nt][2] = v2; ac2[nt][3] = v3;
                s0 += v0 + v1; ss0 += v0 * v0 + v1 * v1;
                s1 += v2 + v3; ss1 += v2 * v2 + v3 * v3;
            }
            #pragma unroll
            for (int o = 1; o <= 2; o <<= 1) {
                s0  += __shfl_xor_sync(0xffffffffu, s0,  o);
                ss0 += __shfl_xor_sync(0xffffffffu, ss0, o);
                s1  += __shfl_xor_sync(0xffffffffu, s1,  o);
                ss1 += __shfl_xor_sync(0xffffffffu, ss1, o);
            }
            float mu0 = s0 * (1.f / 64.f);
            float rs0 = rsqrtf(ss0 * (1.f / 64.f) - mu0 * mu0 + 1e-5f);
            float mu1 = s1 * (1.f / 64.f);
            float rs1 = rsqrtf(ss1 * (1.f / 64.f) - mu1 * mu1 + 1e-5f);

            float p0 = 0.f, p1 = 0.f;
            #pragma unroll
            for (int nt = 0; nt < 8; ++nt) {
                int colb = nt * 8 + 2 * qc;
                float g0 = prm[256 + colb], g1 = prm[256 + colb + 1];
                float e0 = prm[320 + colb], e1 = prm[320 + colb + 1];
                float w0 = prm[384 + colb], w1 = prm[384 + colb + 1];
                float y0 = (ac2[nt][0] - mu0) * rs0 * g0 + e0;
                float y1 = (ac2[nt][1] - mu0) * rs0 * g1 + e1;
                float y2 = (ac2[nt][2] - mu1) * rs1 * g0 + e0;
                float y3 = (ac2[nt][3] - mu1) * rs1 * g1 + e1;
                y0 = (y0 < 0.f) ? 0.1f * y0 : y0;
                y1 = (y1 < 0.f) ? 0.1f * y1 : y1;
                y2 = (y2 < 0.f) ? 0.1f * y2 : y2;
                y3 = (y3 < 0.f) ? 0.1f * y3 : y3;
                p0 += y0 * w0 + y1 * w1;
                p1 += y2 * w0 + y3 * w1;
            }
            #pragma unroll
            for (int o = 1; o <= 2; o <<= 1) {
                p0 += __shfl_xor_sync(0xffffffffu, p0, o);
                p1 += __shfl_xor_sync(0xffffffffu, p1, o);
            }
            if (qc == 0) {
                float b3 = prm[448];
                if (eLo < E) out[eLo] = p0 + b3;
                if (eHi < E) out[eHi] = p1 + b3;
            }
        }
    }
}

extern "C" void kernel_launch(void* const* d_in, const int* in_sizes, int n_in,
                              void* d_out, int out_size)
{
    const float* nodef = (const float*)d_in[0];
    const int*   eidx  = (const int*)d_in[1];   // int32 [2, E]
    const float* eattr = (const float*)d_in[2];
    const float* W1  = (const float*)d_in[3];
    const float* B1  = (const float*)d_in[4];
    const float* G1  = (const float*)d_in[5];
    const float* BE1 = (const float*)d_in[6];
    const float* W2  = (const float*)d_in[7];
    const float* B2  = (const float*)d_in[8];
    const float* G2  = (const float*)d_in[9];
    const float* BE2 = (const float*)d_in[10];
    const float* W3  = (const float*)d_in[11];
    const float* B3  = (const float*)d_in[12];
    float* out = (float*)d_out;

    int E      = out_size;
    int nNodes = in_sizes[0] / 64;
    int nTiles = (E + 127) / 128;
    int grid   = (nTiles + TPB - 1) / TPB;

    edgenet_mma<<<grid, 256>>>(
        nodef, eidx, eattr, W1, B1, G1, BE1, W2, B2, G2, BE2, W3, B3,
        out, E, nNodes);
}

// round 15
// speedup vs baseline: 1.1081x; 1.1081x over previous
#include <cuda_runtime.h>
#include <cuda_fp16.h>
#include <cstdint>

// EdgeNetwork R14 — R12 core (coalesced smem-staged gather, fragment-chained
// LN epilogues, warp-autonomous tiles, 3 CTAs/SM) + R13's B relayout:
// W col n stored at (n&7)*8+(n>>3), stride 66 -> per-thread fragment words
// contiguous -> LDS.64, conflict-free (banks 8qr+2qc+j bijective mod 32).

#define XSW 76    // X row stride (words); fragment reads conflict-free
#define WQS 66    // W pair-row stride (words)
#define TPB 4

#define X_OFF   0
#define W1_OFF  (128 * XSW)                  // 9728
#define W2_OFF  (W1_OFF + 72 * WQS)          // 14480
#define PRM_OFF (W2_OFF + 32 * WQS)          // 16592
#define SMEM_WORDS (PRM_OFF + 452)           // 17044
#define SMEM_BYTES (SMEM_WORDS * 4)          // 68176

__device__ __forceinline__ uint32_t h2pack(float lo, float hi) {
    __half2 h = __floats2half2_rn(lo, hi);
    return *(uint32_t*)&h;
}

#define MMA_F16(d, a, b0, b1) \
    asm volatile("mma.sync.aligned.m16n8k16.row.col.f32.f16.f16.f32 " \
        "{%0,%1,%2,%3}, {%4,%5,%6,%7}, {%8,%9}, {%0,%1,%2,%3};" \
        : "+f"((d)[0]), "+f"((d)[1]), "+f"((d)[2]), "+f"((d)[3]) \
        : "r"((a)[0]), "r"((a)[1]), "r"((a)[2]), "r"((a)[3]), "r"(b0), "r"(b1))

__global__ __launch_bounds__(256, 3)
void edgenet_mma(const float* __restrict__ nodef,
                 const int* __restrict__ eidx,
                 const float* __restrict__ eattr,
                 const float* __restrict__ W1, const float* __restrict__ pB1,
                 const float* __restrict__ G1, const float* __restrict__ BE1,
                 const float* __restrict__ W2, const float* __restrict__ pB2,
                 const float* __restrict__ G2, const float* __restrict__ BE2,
                 const float* __restrict__ W3, const float* __restrict__ pB3,
                 float* __restrict__ out, int E, int nNodes)
{
    extern __shared__ uint32_t smem[];
    uint32_t* Xs  = smem + X_OFF;
    uint32_t* W1q = smem + W1_OFF;
    uint32_t* W2q = smem + W2_OFF;
    float*    prm = (float*)(smem + PRM_OFF);

    const int tid  = threadIdx.x;
    const int lane = tid & 31;
    const int wid  = tid >> 5;
    const int qr   = lane >> 2;
    const int qc   = lane & 3;

    // ---- stage weights (k-pair half2, permuted cols) + params ----
    for (int i = tid; i < 72 * 64; i += 256) {
        int p = i >> 6, n = i & 63;
        W1q[p * WQS + (n & 7) * 8 + (n >> 3)] =
            h2pack(W1[(2 * p) * 64 + n], W1[(2 * p + 1) * 64 + n]);
    }
    for (int i = tid; i < 32 * 64; i += 256) {
        int p = i >> 6, n = i & 63;
        W2q[p * WQS + (n & 7) * 8 + (n >> 3)] =
            h2pack(W2[(2 * p) * 64 + n], W2[(2 * p + 1) * 64 + n]);
    }
    if (tid < 64) {
        prm[tid]       = pB1[tid];
        prm[64 + tid]  = G1[tid];
        prm[128 + tid] = BE1[tid];
        prm[192 + tid] = pB2[tid];
        prm[256 + tid] = G2[tid];
        prm[320 + tid] = BE2[tid];
        prm[384 + tid] = W3[tid];
    }
    if (tid == 0) prm[448] = pB3[0];
    __syncthreads();   // only CTA barrier

    const float4* nf4 = (const float4*)nodef;
    const float4* ea4 = (const float4*)eattr;
    const int rBase = wid * 16;
    const int r0 = rBase + qr;

    for (int it = 0; it < TPB; ++it) {
        const int eBase = (blockIdx.x * TPB + it) * 128;
        if (eBase >= E) break;

        // ---- warp-local coalesced gather of this warp's 16 X rows ----
        #pragma unroll
        for (int half = 0; half < 2; ++half) {
            #pragma unroll
            for (int i = 0; i < 8; ++i) {
                int r  = rBase + i * 2 + (lane >> 4);
                int f4 = lane & 15;
                int eg = eBase + r;
                int node = 0;
                if (eg < E) node = half ? eidx[(size_t)E + eg] : eidx[eg];
                if (node < 0) node = 0;
                if (node >= nNodes) node = nNodes - 1;
                float4 v = nf4[(size_t)node * 16 + f4];
                *(uint2*)(Xs + r * XSW + half * 32 + f4 * 2) =
                    make_uint2(h2pack(v.x, v.y), h2pack(v.z, v.w));
            }
        }
        #pragma unroll
        for (int t2 = 0; t2 < 2; ++t2) {
            int idx = t2 * 32 + lane;
            int r = rBase + (idx >> 2), f4 = idx & 3;
            int eg = eBase + r;
            float4 v = make_float4(0.f, 0.f, 0.f, 0.f);
            if (eg < E) v = ea4[(size_t)eg * 4 + f4];
            *(uint2*)(Xs + r * XSW + 64 + f4 * 2) =
                make_uint2(h2pack(v.x, v.y), h2pack(v.z, v.w));
        }
        __syncwarp();

        // ===== GEMM1: X[16,144] @ W1 =====
        float acc[8][4];
        #pragma unroll
        for (int nt = 0; nt < 8; ++nt)
            #pragma unroll
            for (int x = 0; x < 4; ++x) acc[nt][x] = 0.f;

        #pragma unroll 3
        for (int ks = 0; ks < 9; ++ks) {
            int kw = ks * 8;
            uint32_t a[4];
            const uint32_t* xr = Xs + r0 * XSW + kw + qc;
            a[0] = xr[0];
            a[1] = xr[8 * XSW];
            a[2] = xr[4];
            a[3] = xr[8 * XSW + 4];
            const uint32_t* wbA = W1q + (kw + qc) * WQS + qr * 8;
            const uint32_t* wbB = wbA + 4 * WQS;
            #pragma unroll
            for (int g = 0; g < 4; ++g) {
                uint2 b0 = *(const uint2*)(wbA + 2 * g);
                uint2 b1 = *(const uint2*)(wbB + 2 * g);
                MMA_F16(acc[2 * g],     a, b0.x, b1.x);
                MMA_F16(acc[2 * g + 1], a, b0.y, b1.y);
            }
        }

        // ---- LN1 + leaky, in-register -> GEMM2 A fragments ----
        uint32_t a2[4][4];
        {
            float s0 = 0.f, ss0 = 0.f, s1 = 0.f, ss1 = 0.f;
            #pragma unroll
            for (int nt = 0; nt < 8; ++nt) {
                int colb = nt * 8 + 2 * qc;
                float v0 = acc[nt][0] + prm[colb];
                float v1 = acc[nt][1] + prm[colb + 1];
                float v2 = acc[nt][2] + prm[colb];
                float v3 = acc[nt][3] + prm[colb + 1];
                acc[nt][0] = v0; acc[nt][1] = v1; acc[nt][2] = v2; acc[nt][3] = v3;
                s0 += v0 + v1; ss0 += v0 * v0 + v1 * v1;
                s1 += v2 + v3; ss1 += v2 * v2 + v3 * v3;
            }
            #pragma unroll
            for (int o = 1; o <= 2; o <<= 1) {
                s0  += __shfl_xor_sync(0xffffffffu, s0,  o);
                ss0 += __shfl_xor_sync(0xffffffffu, ss0, o);
                s1  += __shfl_xor_sync(0xffffffffu, s1,  o);
                ss1 += __shfl_xor_sync(0xffffffffu, ss1, o);
            }
            float mu0 = s0 * (1.f / 64.f);
            float rs0 = rsqrtf(ss0 * (1.f / 64.f) - mu0 * mu0 + 1e-5f);
            float mu1 = s1 * (1.f / 64.f);
            float rs1 = rsqrtf(ss1 * (1.f / 64.f) - mu1 * mu1 + 1e-5f);
            #pragma unroll
            for (int nt = 0; nt < 8; ++nt) {
                int colb = nt * 8 + 2 * qc;
                float g0 = prm[64 + colb], g1 = prm[64 + colb + 1];
                float e0 = prm[128 + colb], e1 = prm[128 + colb + 1];
                float y0 = (acc[nt][0] - mu0) * rs0 * g0 + e0;
                float y1 = (acc[nt][1] - mu0) * rs0 * g1 + e1;
                float y2 = (acc[nt][2] - mu1) * rs1 * g0 + e0;
                float y3 = (acc[nt][3] - mu1) * rs1 * g1 + e1;
                y0 = (y0 < 0.f) ? 0.1f * y0 : y0;
                y1 = (y1 < 0.f) ? 0.1f * y1 : y1;
                y2 = (y2 < 0.f) ? 0.1f * y2 : y2;
                y3 = (y3 < 0.f) ? 0.1f * y3 : y3;
                a2[nt >> 1][(nt & 1) * 2]     = h2pack(y0, y1);
                a2[nt >> 1][(nt & 1) * 2 + 1] = h2pack(y2, y3);
            }
        }

        // ===== GEMM2: H[16,64] @ W2 (A in registers) =====
        float ac2[8][4];
        #pragma unroll
        for (int nt = 0; nt < 8; ++nt)
            #pragma unroll
            for (int x = 0; x < 4; ++x) ac2[nt][x] = 0.f;

        #pragma unroll
        for (int ks = 0; ks < 4; ++ks) {
            const uint32_t* wbA = W2q + (ks * 8 + qc) * WQS + qr * 8;
            const uint32_t* wbB = wbA + 4 * WQS;
            #pragma unroll
            for (int g = 0; g < 4; ++g) {
                uint2 b0 = *(const uint2*)(wbA + 2 * g);
                uint2 b1 = *(const uint2*)(wbB + 2 * g);
                MMA_F16(ac2[2 * g],     a2[ks], b0.x, b1.x);
                MMA_F16(ac2[2 * g + 1], a2[ks], b0.y, b1.y);
            }
        }

        // ---- LN2 + leaky + W3 dot + store (shfl-only) ----
        {
            float s0 = 0.f, ss0 = 0.f, s1 = 0.f, ss1 = 0.f;
            #pragma unroll
            for (int nt = 0; nt < 8; ++nt) {
                int colb = nt * 8 + 2 * qc;
                float v0 = ac2[nt][0] + prm[192 + colb];
                float v1 = ac2[nt][1] + prm[192 + colb + 1];
                float v2 = ac2[nt][2] + prm[192 + colb];
                float v3 = ac2[nt][3] + prm[192 + colb + 1];
                ac2[nt][0] = v0; ac2[nt][1] = v1; ac2[nt][2] = v2; ac2[nt][3] = v3;
                s0 += v0 + v1; ss0 += v0 * v0 + v1 * v1;
                s1 += v2 + v3; ss1 += v2 * v2 + v3 * v3;
            }
            #pragma unroll
            for (int o = 1; o <= 2; o <<= 1) {
                s0  += __shfl_xor_sync(0xffffffffu, s0,  o);
                ss0 += __shfl_xor_sync(0xffffffffu, ss0, o);
                s1  += __shfl_xor_sync(0xffffffffu, s1,  o);
                ss1 += __shfl_xor_sync(0xffffffffu, ss1, o);
            }
            float mu0 = s0 * (1.f / 64.f);
            float rs0 = rsqrtf(ss0 * (1.f / 64.f) - mu0 * mu0 + 1e-5f);
            float mu1 = s1 * (1.f / 64.f);
            float rs1 = rsqrtf(ss1 * (1.f / 64.f) - mu1 * mu1 + 1e-5f);

            float p0 = 0.f, p1 = 0.f;
            #pragma unroll
            for (int nt = 0; nt < 8; ++nt) {
                int colb = nt * 8 + 2 * qc;
                float g0 = prm[256 + colb], g1 = prm[256 + colb + 1];
                float e0 = prm[320 + colb], e1 = prm[320 + colb + 1];
                float w0 = prm[384 + colb], w1 = prm[384 + colb + 1];
                float y0 = (ac2[nt][0] - mu0) * rs0 * g0 + e0;
                float y1 = (ac2[nt][1] - mu0) * rs0 * g1 + e1;
                float y2 = (ac2[nt][2] - mu1) * rs1 * g0 + e0;
                float y3 = (ac2[nt][3] - mu1) * rs1 * g1 + e1;
                y0 = (y0 < 0.f) ? 0.1f * y0 : y0;
                y1 = (y1 < 0.f) ? 0.1f * y1 : y1;
                y2 = (y2 < 0.f) ? 0.1f * y2 : y2;
                y3 = (y3 < 0.f) ? 0.1f * y3 : y3;
                p0 += y0 * w0 + y1 * w1;
                p1 += y2 * w0 + y3 * w1;
            }
            #pragma unroll
            for (int o = 1; o <= 2; o <<= 1) {
                p0 += __shfl_xor_sync(0xffffffffu, p0, o);
                p1 += __shfl_xor_sync(0xffffffffu, p1, o);
            }
            if (qc == 0) {
                float b3 = prm[448];
                int e0i = eBase + r0;
                int e1i = eBase + r0 + 8;
                if (e0i < E) out[e0i] = p0 + b3;
                if (e1i < E) out[e1i] = p1 + b3;
            }
        }
        __syncwarp();   // X rows warp-private; safe to regather next tile
    }
}

extern "C" void kernel_launch(void* const* d_in, const int* in_sizes, int n_in,
                              void* d_out, int out_size)
{
    const float* nodef = (const float*)d_in[0];
    const int*   eidx  = (const int*)d_in[1];   // int32 [2, E]
    const float* eattr = (const float*)d_in[2];
    const float* W1  = (const float*)d_in[3];
    const float* B1  = (const float*)d_in[4];
    const float* G1  = (const float*)d_in[5];
    const float* BE1 = (const float*)d_in[6];
    const float* W2  = (const float*)d_in[7];
    const float* B2  = (const float*)d_in[8];
    const float* G2  = (const float*)d_in[9];
    const float* BE2 = (const float*)d_in[10];
    const float* W3  = (const float*)d_in[11];
    const float* B3  = (const float*)d_in[12];
    float* out = (float*)d_out;

    int E      = out_size;
    int nNodes = in_sizes[0] / 64;
    int nTiles = (E + 127) / 128;
    int grid   = (nTiles + TPB - 1) / TPB;

    cudaFuncSetAttribute(edgenet_mma,
                         cudaFuncAttributeMaxDynamicSharedMemorySize, SMEM_BYTES);
    edgenet_mma<<<grid, 256, SMEM_BYTES>>>(
        nodef, eidx, eattr, W1, B1, G1, BE1, W2, B2, G2, BE2, W3, B3,
        out, E, nNodes);
}